// round 1
// baseline (speedup 1.0000x reference)
#include <cuda_runtime.h>
#include <math.h>

#define BB   4
#define NN   1024
#define KNN  30
#define MM   8
#define CINV 9
#define OO   64
#define FE   320
#define PC   512          // M*O
#define BN_SCALE 0.99999500003749972f

// ---------------- device scratch (no allocs allowed) ----------------
__device__ float g_xt[BB*NN*CINV];
__device__ float g_sq[BB*NN];
__device__ int   g_idx[BB*NN*KNN];
__device__ float g_xyz[BB*NN*KNN*28];
__device__ float g_feats[BB*NN*FE];
__device__ float g_point[BB*NN*PC];
__device__ float g_center[BB*NN*PC];
__device__ float g_wT[FE*PC];

// ---------------- 1) transpose + sq ----------------
__global__ void k_prep(const float* __restrict__ x){
    int t = blockIdx.x*blockDim.x + threadIdx.x;
    if (t >= BB*NN) return;
    int b = t >> 10, n = t & 1023;
    float s = 0.f;
#pragma unroll
    for (int c = 0; c < CINV; c++){
        float v = x[(b*CINV + c)*NN + n];
        g_xt[t*CINV + c] = v;
        s += v*v;
    }
    g_sq[t] = s;
}

// ---------------- 2) knn top-K ----------------
__global__ void k_knn(){
    __shared__ float sh[128*CINV];
    __shared__ float shsq[128];
    int b = blockIdx.x >> 3;
    int i = ((blockIdx.x & 7) << 7) + threadIdx.x;
    int bn = b*NN + i;
    float c[CINV];
#pragma unroll
    for (int t = 0; t < CINV; t++) c[t] = g_xt[bn*CINV + t];
    float sqi = g_sq[bn];
    float bv[KNN]; int bi[KNN];
#pragma unroll
    for (int t = 0; t < KNN; t++){ bv[t] = -3.4e38f; bi[t] = 0; }
    for (int jt = 0; jt < NN; jt += 128){
        __syncthreads();
        for (int q = threadIdx.x; q < 128*CINV; q += 128)
            sh[q] = g_xt[(b*NN + jt)*CINV + q];
        shsq[threadIdx.x] = g_sq[b*NN + jt + threadIdx.x];
        __syncthreads();
        for (int jj = 0; jj < 128; jj++){
            float d = 0.f;
#pragma unroll
            for (int t = 0; t < CINV; t++) d += c[t]*sh[jj*CINV + t];
            float v = 2.0f*d - sqi - shsq[jj];
            if (v > bv[KNN-1]){
                int p = KNN-1;
                while (p > 0 && bv[p-1] < v){
                    bv[p] = bv[p-1]; bi[p] = bi[p-1]; p--;
                }
                bv[p] = v; bi[p] = jt + jj;
            }
        }
    }
    for (int t = 0; t < KNN; t++) g_idx[bn*KNN + t] = bi[t];
}

// ---------------- 3) xyz build + conv1 -> bn -> relu -> max_k ----------------
__global__ void k_edge(const float* __restrict__ w1, const float* __restrict__ b1){
    int bn = blockIdx.x;
    int b  = bn >> 10;
    int tid = threadIdx.x;
    __shared__ float sgf[KNN][18];
    __shared__ float sctr[CINV];
    if (tid < CINV) sctr[tid] = g_xt[bn*CINV + tid];
    __syncthreads();
    if (tid < KNN){
        int j = g_idx[bn*KNN + tid];
        float nb[CINV], df[CINV]; float ss = 0.f;
#pragma unroll
        for (int t = 0; t < CINV; t++){
            nb[t] = g_xt[(b*NN + j)*CINV + t];
            df[t] = nb[t] - sctr[t];
            ss += df[t]*df[t];
        }
        float ed = sqrtf(ss);
        float* xz = &g_xyz[(bn*KNN + tid)*28];
#pragma unroll
        for (int t = 0; t < CINV; t++){
            xz[t]      = df[t];
            xz[9 + t]  = nb[t];
            xz[18 + t] = sctr[t];
            sgf[tid][t]     = df[t];
            sgf[tid][9 + t] = sctr[t];
        }
        xz[27] = ed;
    }
    __syncthreads();
    int o = tid;                       // 64 output channels
    float w[18];
#pragma unroll
    for (int t = 0; t < 18; t++) w[t] = w1[o*18 + t];
    float bias = b1[o];
    float mx = 0.f;
    for (int k = 0; k < KNN; k++){
        float d = bias;
#pragma unroll
        for (int t = 0; t < 18; t++) d += sgf[k][t]*w[t];
        mx = fmaxf(mx, d*BN_SCALE);    // relu folded (mx init 0)
    }
    g_feats[bn*FE + o] = mx;
}

// ---------------- 4a) point & center GEMM (per layer) ----------------
__global__ void k_point(const float* __restrict__ mats, int l){
    __shared__ float sf[16][OO];
    int p0 = blockIdx.x*16;
    int j  = threadIdx.x;              // 512 output columns
    for (int q = threadIdx.x; q < 16*OO; q += 512)
        sf[q >> 6][q & 63] = g_feats[(p0 + (q >> 6))*FE + l*OO + (q & 63)];
    __syncthreads();
    const float* kern = mats + l*128*PC;
    float a1[16], a2[16];
#pragma unroll
    for (int r = 0; r < 16; r++){ a1[r] = 0.f; a2[r] = 0.f; }
    for (int c4 = 0; c4 < 16; c4++){
        int c = c4*4;
        float k10 = kern[(c+0)*PC + j], k11 = kern[(c+1)*PC + j];
        float k12 = kern[(c+2)*PC + j], k13 = kern[(c+3)*PC + j];
        float k20 = kern[(c+64)*PC + j], k21 = kern[(c+65)*PC + j];
        float k22 = kern[(c+66)*PC + j], k23 = kern[(c+67)*PC + j];
#pragma unroll
        for (int r = 0; r < 16; r++){
            float4 f4 = *(const float4*)&sf[r][c];
            a1[r] += f4.x*k10 + f4.y*k11 + f4.z*k12 + f4.w*k13;
            a2[r] += f4.x*k20 + f4.y*k21 + f4.z*k22 + f4.w*k23;
        }
    }
#pragma unroll
    for (int r = 0; r < 16; r++){
        g_center[(p0 + r)*PC + j] = a1[r];
        g_point [(p0 + r)*PC + j] = a1[r] + a2[r];
    }
}

// ---------------- 4b) scorenet + assemble + bn/relu (per layer) ----------------
__global__ void k_asm(const float* __restrict__ hw, const float* __restrict__ ow,
                      const float* __restrict__ ob, int l){
    int bn = blockIdx.x;
    int b  = bn >> 10;
    int tid = threadIdx.x;
    __shared__ float s_hw[16*28];
    __shared__ float s_ow[8*16];
    __shared__ float s_ob[8];
    __shared__ float s_sc[KNN][8];
    __shared__ float s_S[8];
    __shared__ int   s_j[KNN];
    const float* hwl = hw + l*16*28;
    const float* owl = ow + l*8*16;
    for (int q = tid; q < 448; q += 64) s_hw[q] = hwl[q];
    for (int q = tid; q < 128; q += 64) s_ow[q] = owl[q];
    if (tid < 8)  s_ob[tid] = ob[l*8 + tid];
    if (tid < KNN) s_j[tid] = g_idx[bn*KNN + tid];
    __syncthreads();
    if (tid < KNN){
        const float* xz = &g_xyz[(bn*KNN + tid)*28];
        float xr[28];
#pragma unroll
        for (int t = 0; t < 28; t++) xr[t] = xz[t];
        float hid[16];
#pragma unroll
        for (int h = 0; h < 16; h++){
            float d = 0.f;
#pragma unroll
            for (int t = 0; t < 28; t++) d += xr[t]*s_hw[h*28 + t];
            hid[h] = fmaxf(d*BN_SCALE, 0.f);
        }
        float lg[8]; float mxl = -3.4e38f;
#pragma unroll
        for (int m = 0; m < 8; m++){
            float d = s_ob[m];
#pragma unroll
            for (int h = 0; h < 16; h++) d += hid[h]*s_ow[m*16 + h];
            lg[m] = d;
            mxl = fmaxf(mxl, d);
        }
        float se = 0.f;
#pragma unroll
        for (int m = 0; m < 8; m++){ lg[m] = expf(lg[m] - mxl); se += lg[m]; }
        float inv = 1.0f/se;
#pragma unroll
        for (int m = 0; m < 8; m++) s_sc[tid][m] = lg[m]*inv;
    }
    __syncthreads();
    if (tid < 8){
        float s = 0.f;
        for (int k = 0; k < KNN; k++) s += s_sc[k][tid];
        s_S[tid] = s;
    }
    __syncthreads();
    int o = tid;                       // 64 output channels
    float acc = 0.f;
    for (int k = 0; k < KNN; k++){
        const float* pr = &g_point[(b*NN + s_j[k])*PC + o];
#pragma unroll
        for (int m = 0; m < 8; m++) acc += s_sc[k][m]*pr[m*OO];
    }
    const float* cr = &g_center[bn*PC + o];
#pragma unroll
    for (int m = 0; m < 8; m++) acc -= s_S[m]*cr[m*OO];
    g_feats[bn*FE + (l+1)*OO + o] = fmaxf(acc*BN_SCALE, 0.f);
}

// ---------------- 5) weight transpose, zero out, final GEMM + max ----------------
__global__ void k_wt(const float* __restrict__ w){   // (512,320) -> (320,512)
    int t = blockIdx.x*blockDim.x + threadIdx.x;
    if (t < FE*PC){
        int c = t >> 9, o = t & 511;
        g_wT[t] = w[o*FE + c];
    }
}

__global__ void k_zero(float* __restrict__ out){
    int t = blockIdx.x*blockDim.x + threadIdx.x;
    if (t < BB*PC) out[t] = 0.f;
}

__global__ void k_final(float* __restrict__ out){
    __shared__ float sxx[32][FE];      // 40 KB
    int p0 = blockIdx.x*32;
    int b  = p0 >> 10;
    int o  = threadIdx.x;              // 512 columns
    for (int q = threadIdx.x; q < 32*FE; q += 512)
        sxx[q/FE][q%FE] = g_feats[p0*FE + q];
    __syncthreads();
    float acc[32];
#pragma unroll
    for (int r = 0; r < 32; r++) acc[r] = 0.f;
    for (int c4 = 0; c4 < FE/4; c4++){
        int c = c4*4;
        float w0 = g_wT[(c+0)*PC + o];
        float w1 = g_wT[(c+1)*PC + o];
        float w2 = g_wT[(c+2)*PC + o];
        float w3 = g_wT[(c+3)*PC + o];
#pragma unroll
        for (int r = 0; r < 32; r++){
            float4 x4 = *(const float4*)&sxx[r][c];
            acc[r] += x4.x*w0 + x4.y*w1 + x4.z*w2 + x4.w*w3;
        }
    }
    float mx = 0.f;
#pragma unroll
    for (int r = 0; r < 32; r++) mx = fmaxf(mx, acc[r]*BN_SCALE);  // relu folded
    atomicMax((int*)&out[b*PC + o], __float_as_int(mx));           // nonneg floats
}

// ---------------- launch ----------------
extern "C" void kernel_launch(void* const* d_in, const int* in_sizes, int n_in,
                              void* d_out, int out_size){
    const float* x       = (const float*)d_in[0];
    const float* conv1_w = (const float*)d_in[3];
    const float* conv1_b = (const float*)d_in[4];
    const float* sn_hw   = (const float*)d_in[5];
    const float* sn_ow   = (const float*)d_in[6];
    const float* sn_ob   = (const float*)d_in[7];
    const float* mats    = (const float*)d_in[8];
    const float* convt_w = (const float*)d_in[9];
    float* out = (float*)d_out;

    k_prep<<<(BB*NN + 255)/256, 256>>>(x);
    k_knn<<<BB*8, 128>>>();
    k_edge<<<BB*NN, 64>>>(conv1_w, conv1_b);
    for (int l = 0; l < 4; l++){
        k_point<<<BB*NN/16, 512>>>(mats, l);
        k_asm<<<BB*NN, 64>>>(sn_hw, sn_ow, sn_ob, l);
    }
    k_wt<<<(FE*PC + 255)/256, 256>>>(convt_w);
    k_zero<<<(BB*PC + 255)/256, 256>>>(out);
    k_final<<<BB*NN/32, 512>>>(out);
}

// round 2
// speedup vs baseline: 2.2349x; 2.2349x over previous
#include <cuda_runtime.h>
#include <math.h>

#define BB   4
#define NN   1024
#define KNN  30
#define MM   8
#define CINV 9
#define OO   64
#define FE   320
#define PC   512          // M*O
#define BN_SCALE 0.99999500003749972f

// ---------------- device scratch (no allocs allowed) ----------------
__device__ float g_xt[BB*NN*CINV];
__device__ float g_sq[BB*NN];
__device__ int   g_idx[BB*NN*KNN];
__device__ float g_xyz[BB*NN*KNN*28];
__device__ float g_feats[BB*NN*FE];
__device__ float g_point[BB*NN*PC];
__device__ float g_center[BB*NN*PC];
__device__ float g_kT[4*PC*128];       // mats transposed: [l][j][c]

// ---------------- 1) transpose + sq ----------------
__global__ void k_prep(const float* __restrict__ x){
    int t = blockIdx.x*blockDim.x + threadIdx.x;
    if (t >= BB*NN) return;
    int b = t >> 10, n = t & 1023;
    float s = 0.f;
#pragma unroll
    for (int c = 0; c < CINV; c++){
        float v = x[(b*CINV + c)*NN + n];
        g_xt[t*CINV + c] = v;
        s += v*v;
    }
    g_sq[t] = s;
}

// ---------------- 1b) transpose mats: [l][c][j] -> [l][j][c] ----------------
__global__ void k_ktr(const float* __restrict__ mats){
    int t = blockIdx.x*blockDim.x + threadIdx.x;   // 4*512*128
    if (t >= 4*PC*128) return;
    int l = t >> 16;
    int j = (t >> 7) & 511;
    int c = t & 127;
    g_kT[t] = mats[(l << 16) + c*PC + j];
}

// ---------------- 2) knn top-K: block per point, argmax extraction ----------------
__global__ void k_knn(){
    __shared__ unsigned long long keys[NN];   // 8KB
    __shared__ unsigned long long wmax[8];
    __shared__ float sc[CINV];
    int bn  = blockIdx.x;
    int b   = bn >> 10;
    int tid = threadIdx.x;                    // 256
    if (tid < CINV) sc[tid] = g_xt[bn*CINV + tid];
    __syncthreads();
    float c[CINV];
#pragma unroll
    for (int t = 0; t < CINV; t++) c[t] = sc[t];
    float sqi = g_sq[bn];
    for (int j = tid; j < NN; j += 256){
        const float* p = &g_xt[(b*NN + j)*CINV];
        float d = 0.f;
#pragma unroll
        for (int t = 0; t < CINV; t++) d += c[t]*p[t];
        float v = 2.0f*d - sqi - g_sq[b*NN + j];
        int iv = __float_as_int(v);
        unsigned int u = (iv >= 0) ? ((unsigned)iv | 0x80000000u) : ~((unsigned)iv);
        keys[j] = ((unsigned long long)u << 32) | (unsigned)(NN - j);
    }
    __syncthreads();
    for (int s = 0; s < KNN; s++){
        unsigned long long m = 0ULL;
#pragma unroll
        for (int r = 0; r < NN/256; r++){
            unsigned long long kk = keys[tid + r*256];
            if (kk > m) m = kk;
        }
#pragma unroll
        for (int off = 16; off; off >>= 1){
            unsigned long long o = __shfl_down_sync(0xFFFFFFFFu, m, off);
            if (o > m) m = o;
        }
        if ((tid & 31) == 0) wmax[tid >> 5] = m;
        __syncthreads();
        if (tid == 0){
            unsigned long long mm = wmax[0];
#pragma unroll
            for (int w = 1; w < 8; w++) if (wmax[w] > mm) mm = wmax[w];
            int j = NN - (int)(mm & 0xFFFFFFFFULL);
            g_idx[bn*KNN + s] = j;
            keys[j] = 0ULL;
        }
        __syncthreads();
    }
}

// ---------------- 3) xyz build + conv1 -> bn -> relu -> max_k ----------------
__global__ void k_edge(const float* __restrict__ w1, const float* __restrict__ b1){
    int bn = blockIdx.x;
    int b  = bn >> 10;
    int tid = threadIdx.x;
    __shared__ float sgf[KNN][18];
    __shared__ float sctr[CINV];
    if (tid < CINV) sctr[tid] = g_xt[bn*CINV + tid];
    __syncthreads();
    if (tid < KNN){
        int j = g_idx[bn*KNN + tid];
        float nb[CINV], df[CINV]; float ss = 0.f;
#pragma unroll
        for (int t = 0; t < CINV; t++){
            nb[t] = g_xt[(b*NN + j)*CINV + t];
            df[t] = nb[t] - sctr[t];
            ss += df[t]*df[t];
        }
        float ed = sqrtf(ss);
        float* xz = &g_xyz[(bn*KNN + tid)*28];
#pragma unroll
        for (int t = 0; t < CINV; t++){
            xz[t]      = df[t];
            xz[9 + t]  = nb[t];
            xz[18 + t] = sctr[t];
            sgf[tid][t]     = df[t];
            sgf[tid][9 + t] = sctr[t];
        }
        xz[27] = ed;
    }
    __syncthreads();
    int o = tid;                       // 64 output channels
    float w[18];
#pragma unroll
    for (int t = 0; t < 18; t++) w[t] = w1[o*18 + t];
    float bias = b1[o];
    float mx = 0.f;
    for (int k = 0; k < KNN; k++){
        float d = bias;
#pragma unroll
        for (int t = 0; t < 18; t++) d += sgf[k][t]*w[t];
        mx = fmaxf(mx, d*BN_SCALE);    // relu folded (mx init 0)
    }
    g_feats[bn*FE + o] = mx;
}

// ---------------- 4a) point & center GEMM (per layer) ----------------
__global__ void k_point(int l){
    __shared__ float sf[16][OO];
    int p0 = blockIdx.x*16;
    int j  = threadIdx.x;              // 512 output columns
    for (int q = threadIdx.x; q < 16*OO; q += 512)
        sf[q >> 6][q & 63] = g_feats[(p0 + (q >> 6))*FE + l*OO + (q & 63)];
    __syncthreads();
    const float* kT = g_kT + (l << 16) + j*128;
    float a1[16], a2[16];
#pragma unroll
    for (int r = 0; r < 16; r++){ a1[r] = 0.f; a2[r] = 0.f; }
#pragma unroll 4
    for (int c4 = 0; c4 < 16; c4++){
        int cc = c4*4;
        float4 kA = *(const float4*)(kT + cc);
        float4 kB = *(const float4*)(kT + 64 + cc);
#pragma unroll
        for (int r = 0; r < 16; r++){
            float4 f4 = *(const float4*)&sf[r][cc];
            a1[r] += f4.x*kA.x + f4.y*kA.y + f4.z*kA.z + f4.w*kA.w;
            a2[r] += f4.x*kB.x + f4.y*kB.y + f4.z*kB.z + f4.w*kB.w;
        }
    }
#pragma unroll
    for (int r = 0; r < 16; r++){
        g_center[(p0 + r)*PC + j] = a1[r];
        g_point [(p0 + r)*PC + j] = a1[r] + a2[r];
    }
}

// ---------------- 4b) scorenet + assemble + bn/relu (per layer) ----------------
__global__ void k_asm(const float* __restrict__ hw, const float* __restrict__ ow,
                      const float* __restrict__ ob, int l){
    int bn = blockIdx.x;
    int b  = bn >> 10;
    int tid = threadIdx.x;             // 128
    __shared__ float s_hw[448];
    __shared__ float s_ow[128];
    __shared__ float s_ob[8];
    __shared__ float s_sc[KNN][8];
    __shared__ float s_S[8];
    __shared__ int   s_j[KNN];
    __shared__ float4 s_part[8][16];
    const float* hwl = hw + l*448;
    const float* owl = ow + l*128;
    for (int q = tid; q < 448; q += 128) s_hw[q] = hwl[q];
    s_ow[tid] = owl[tid & 127];
    if (tid < 8)   s_ob[tid] = ob[l*8 + tid];
    if (tid < KNN) s_j[tid]  = g_idx[bn*KNN + tid];
    __syncthreads();
    if (tid < KNN){
        const float* xz = &g_xyz[(bn*KNN + tid)*28];
        float xr[28];
#pragma unroll
        for (int t = 0; t < 28; t++) xr[t] = xz[t];
        float hid[16];
#pragma unroll
        for (int h = 0; h < 16; h++){
            float d = 0.f;
#pragma unroll
            for (int t = 0; t < 28; t++) d += xr[t]*s_hw[h*28 + t];
            hid[h] = fmaxf(d*BN_SCALE, 0.f);
        }
        float lg[8]; float mxl = -3.4e38f;
#pragma unroll
        for (int m = 0; m < 8; m++){
            float d = s_ob[m];
#pragma unroll
            for (int h = 0; h < 16; h++) d += hid[h]*s_ow[m*16 + h];
            lg[m] = d;
            mxl = fmaxf(mxl, d);
        }
        float se = 0.f;
#pragma unroll
        for (int m = 0; m < 8; m++){ lg[m] = expf(lg[m] - mxl); se += lg[m]; }
        float inv = 1.0f/se;
#pragma unroll
        for (int m = 0; m < 8; m++) s_sc[tid][m] = lg[m]*inv;
    }
    __syncthreads();
    if (tid < 8){
        float s = 0.f;
        for (int k = 0; k < KNN; k++) s += s_sc[k][tid];
        s_S[tid] = s;
    }
    // gather: 16 o-quads x 8-way k split
    int q  = tid & 15;                 // o-quad -> channels 4q..4q+3
    int kp = tid >> 4;                 // k partition 0..7
    float4 acc = make_float4(0.f, 0.f, 0.f, 0.f);
    for (int k = kp; k < KNN; k += 8){
        const float* pr = &g_point[(b*NN + s_j[k])*PC + 4*q];
#pragma unroll
        for (int m = 0; m < 8; m++){
            float s = s_sc[k][m];
            float4 p4 = *(const float4*)(pr + m*OO);
            acc.x += s*p4.x; acc.y += s*p4.y; acc.z += s*p4.z; acc.w += s*p4.w;
        }
    }
    s_part[kp][q] = acc;
    __syncthreads();
    if (tid < OO){
        int o = tid, qq = o >> 2, cc = o & 3;
        float a = 0.f;
#pragma unroll
        for (int kp2 = 0; kp2 < 8; kp2++){
            const float* pp = (const float*)&s_part[kp2][qq];
            a += pp[cc];
        }
        const float* cr = &g_center[bn*PC + o];
#pragma unroll
        for (int m = 0; m < 8; m++) a -= s_S[m]*cr[m*OO];
        g_feats[bn*FE + (l+1)*OO + o] = fmaxf(a*BN_SCALE, 0.f);
    }
}

// ---------------- 5) zero out + final GEMM + max ----------------
__global__ void k_zero(float* __restrict__ out){
    int t = blockIdx.x*blockDim.x + threadIdx.x;
    if (t < BB*PC) out[t] = 0.f;
}

__global__ void k_final(const float* __restrict__ convt_w, float* __restrict__ out){
    __shared__ float sxx[32][FE];      // 40 KB
    int p0 = blockIdx.x*32;
    int b  = p0 >> 10;
    int o  = threadIdx.x;              // 512 columns
    {
        const float4* src = (const float4*)(g_feats + p0*FE);
        float4* dst = (float4*)&sxx[0][0];
        for (int q = threadIdx.x; q < 32*FE/4; q += 512) dst[q] = src[q];
    }
    __syncthreads();
    float acc[32];
#pragma unroll
    for (int r = 0; r < 32; r++) acc[r] = 0.f;
    const float* w = convt_w + o*FE;
#pragma unroll 4
    for (int c4 = 0; c4 < FE/4; c4++){
        int cc = c4*4;
        float4 w4 = *(const float4*)(w + cc);
#pragma unroll
        for (int r = 0; r < 32; r++){
            float4 x4 = *(const float4*)&sxx[r][cc];
            acc[r] += x4.x*w4.x + x4.y*w4.y + x4.z*w4.z + x4.w*w4.w;
        }
    }
    float mx = 0.f;
#pragma unroll
    for (int r = 0; r < 32; r++) mx = fmaxf(mx, acc[r]*BN_SCALE);  // relu folded
    atomicMax((int*)&out[b*PC + o], __float_as_int(mx));           // nonneg floats
}

// ---------------- launch ----------------
extern "C" void kernel_launch(void* const* d_in, const int* in_sizes, int n_in,
                              void* d_out, int out_size){
    const float* x       = (const float*)d_in[0];
    const float* conv1_w = (const float*)d_in[3];
    const float* conv1_b = (const float*)d_in[4];
    const float* sn_hw   = (const float*)d_in[5];
    const float* sn_ow   = (const float*)d_in[6];
    const float* sn_ob   = (const float*)d_in[7];
    const float* mats    = (const float*)d_in[8];
    const float* convt_w = (const float*)d_in[9];
    float* out = (float*)d_out;

    k_prep<<<(BB*NN + 255)/256, 256>>>(x);
    k_ktr<<<(4*PC*128 + 255)/256, 256>>>(mats);
    k_knn<<<BB*NN, 256>>>();
    k_edge<<<BB*NN, 64>>>(conv1_w, conv1_b);
    for (int l = 0; l < 4; l++){
        k_point<<<BB*NN/16, 512>>>(l);
        k_asm<<<BB*NN, 128>>>(sn_hw, sn_ow, sn_ob, l);
    }
    k_zero<<<(BB*PC + 255)/256, 256>>>(out);
    k_final<<<BB*NN/32, 512>>>(convt_w, out);
}

// round 4
// speedup vs baseline: 2.2592x; 1.0109x over previous
#include <cuda_runtime.h>
#include <math.h>

#define BB   4
#define NN   1024
#define KNN  30
#define MM   8
#define CINV 9
#define OO   64
#define FE   320
#define PC   512          // M*O
#define BN_SCALE 0.99999500003749972f

// ---------------- device scratch (no allocs allowed) ----------------
__device__ float g_xt[BB*NN*CINV];
__device__ float g_sq[BB*NN];
__device__ int   g_idx[BB*NN*KNN];
__device__ float g_feats[BB*NN*FE];
__device__ float g_point[BB*NN*PC];
__device__ float g_center[BB*NN*PC];
__device__ float g_kT[4*PC*128];           // mats transposed: [l][j][c]
__device__ float g_score[4*BB*NN*KNN*MM];  // [l][bn][k][m]

// ---------------- 1) transpose + sq (+ zero out) ----------------
__global__ void k_prep(const float* __restrict__ x, float* __restrict__ out){
    int t = blockIdx.x*blockDim.x + threadIdx.x;
    if (t < BB*PC) out[t] = 0.f;
    if (t >= BB*NN) return;
    int b = t >> 10, n = t & 1023;
    float s = 0.f;
#pragma unroll
    for (int c = 0; c < CINV; c++){
        float v = x[(b*CINV + c)*NN + n];
        g_xt[t*CINV + c] = v;
        s += v*v;
    }
    g_sq[t] = s;
}

// ---------------- 1b) transpose mats: [l][c][j] -> [l][j][c] ----------------
__global__ void k_ktr(const float* __restrict__ mats){
    int t = blockIdx.x*blockDim.x + threadIdx.x;   // 4*512*128
    if (t >= 4*PC*128) return;
    int l = t >> 16;
    int j = (t >> 7) & 511;
    int c = t & 127;
    g_kT[t] = mats[(l << 16) + c*PC + j];
}

// ---------------- 2) knn top-K: block per point, argmax extraction ----------------
__global__ void k_knn(){
    __shared__ unsigned long long keys[NN];   // 8KB
    __shared__ unsigned long long wmax[8];
    __shared__ float sc[CINV];
    int bn  = blockIdx.x;
    int b   = bn >> 10;
    int tid = threadIdx.x;                    // 256
    if (tid < CINV) sc[tid] = g_xt[bn*CINV + tid];
    __syncthreads();
    float c[CINV];
#pragma unroll
    for (int t = 0; t < CINV; t++) c[t] = sc[t];
    float sqi = g_sq[bn];
    for (int j = tid; j < NN; j += 256){
        const float* p = &g_xt[(b*NN + j)*CINV];
        float d = 0.f;
#pragma unroll
        for (int t = 0; t < CINV; t++) d += c[t]*p[t];
        float v = 2.0f*d - sqi - g_sq[b*NN + j];
        int iv = __float_as_int(v);
        unsigned int u = (iv >= 0) ? ((unsigned)iv | 0x80000000u) : ~((unsigned)iv);
        keys[j] = ((unsigned long long)u << 32) | (unsigned)(NN - j);
    }
    __syncthreads();
    for (int s = 0; s < KNN; s++){
        unsigned long long m = 0ULL;
#pragma unroll
        for (int r = 0; r < NN/256; r++){
            unsigned long long kk = keys[tid + r*256];
            if (kk > m) m = kk;
        }
#pragma unroll
        for (int off = 16; off; off >>= 1){
            unsigned long long o = __shfl_down_sync(0xFFFFFFFFu, m, off);
            if (o > m) m = o;
        }
        if ((tid & 31) == 0) wmax[tid >> 5] = m;
        __syncthreads();
        if (tid == 0){
            unsigned long long mm = wmax[0];
#pragma unroll
            for (int w = 1; w < 8; w++) if (wmax[w] > mm) mm = wmax[w];
            int j = NN - (int)(mm & 0xFFFFFFFFULL);
            g_idx[bn*KNN + s] = j;
            keys[j] = 0ULL;
        }
        __syncthreads();
    }
}

// ---------------- 3) xyz (shared only) + conv1-max + scorenet all 4 layers ----------------
__global__ void k_edge(const float* __restrict__ w1, const float* __restrict__ b1,
                       const float* __restrict__ hw, const float* __restrict__ ow,
                       const float* __restrict__ ob){
    int bn = blockIdx.x;
    int b  = bn >> 10;
    int tid = threadIdx.x;                 // 128
    __shared__ float s_xyz[KNN][28];
    __shared__ float s_gf[KNN][18];
    __shared__ float s_w1[64*18];
    __shared__ float s_b1[64];
    __shared__ float s_hw[4*448];
    __shared__ float s_ow[4*128];
    __shared__ float s_ob[32];
    __shared__ float sctr[CINV];
    for (int q = tid; q < 64*18; q += 128) s_w1[q] = w1[q];
    if (tid < 64) s_b1[tid] = b1[tid];
    for (int q = tid; q < 4*448; q += 128) s_hw[q] = hw[q];
    for (int q = tid; q < 4*128; q += 128) s_ow[q] = ow[q];
    if (tid < 32) s_ob[tid] = ob[tid];
    if (tid < CINV) sctr[tid] = g_xt[bn*CINV + tid];
    __syncthreads();
    if (tid < KNN){
        int j = g_idx[bn*KNN + tid];
        float nb[CINV], df[CINV]; float ss = 0.f;
#pragma unroll
        for (int t = 0; t < CINV; t++){
            nb[t] = g_xt[(b*NN + j)*CINV + t];
            df[t] = nb[t] - sctr[t];
            ss += df[t]*df[t];
        }
#pragma unroll
        for (int t = 0; t < CINV; t++){
            s_xyz[tid][t]      = df[t];
            s_xyz[tid][9 + t]  = nb[t];
            s_xyz[tid][18 + t] = sctr[t];
            s_gf[tid][t]       = df[t];
            s_gf[tid][9 + t]   = sctr[t];
        }
        s_xyz[tid][27] = sqrtf(ss);
    }
    __syncthreads();
    // conv1 -> bn -> relu -> max over k  (threads 0..63)
    if (tid < OO){
        int o = tid;
        float w[18];
#pragma unroll
        for (int t = 0; t < 18; t++) w[t] = s_w1[o*18 + t];
        float bias = s_b1[o];
        float mx = 0.f;
        for (int k = 0; k < KNN; k++){
            float d = bias;
#pragma unroll
            for (int t = 0; t < 18; t++) d += s_gf[k][t]*w[t];
            mx = fmaxf(mx, d*BN_SCALE);
        }
        g_feats[bn*FE + o] = mx;
    }
    // scorenet for all 4 layers  (threads 0..119: l = tid/30, k = tid%30)
    if (tid < 4*KNN){
        int l = tid / KNN;
        int k = tid - l*KNN;
        const float* hwl = &s_hw[l*448];
        const float* owl = &s_ow[l*128];
        float hid[16];
#pragma unroll
        for (int h = 0; h < 16; h++){
            float d = 0.f;
#pragma unroll
            for (int t = 0; t < 28; t++) d += s_xyz[k][t]*hwl[h*28 + t];
            hid[h] = fmaxf(d*BN_SCALE, 0.f);
        }
        float lg[8]; float mxl = -3.4e38f;
#pragma unroll
        for (int m = 0; m < 8; m++){
            float d = s_ob[l*8 + m];
#pragma unroll
            for (int h = 0; h < 16; h++) d += hid[h]*owl[m*16 + h];
            lg[m] = d;
            mxl = fmaxf(mxl, d);
        }
        float se = 0.f;
#pragma unroll
        for (int m = 0; m < 8; m++){ lg[m] = expf(lg[m] - mxl); se += lg[m]; }
        float inv = 1.0f/se;
        float* dst = &g_score[((l*BB*NN + bn)*KNN + k)*MM];
#pragma unroll
        for (int m = 0; m < 8; m++) dst[m] = lg[m]*inv;
    }
}

// ---------------- 4a) point & center GEMM (per layer) ----------------
__global__ void k_point(int l){
    __shared__ float sf[16][OO];
    int p0 = blockIdx.x*16;
    int j  = threadIdx.x;              // 512 output columns
    for (int q = threadIdx.x; q < 16*OO; q += 512)
        sf[q >> 6][q & 63] = g_feats[(p0 + (q >> 6))*FE + l*OO + (q & 63)];
    __syncthreads();
    const float* kT = g_kT + (l << 16) + j*128;
    float a1[16], a2[16];
#pragma unroll
    for (int r = 0; r < 16; r++){ a1[r] = 0.f; a2[r] = 0.f; }
#pragma unroll 4
    for (int c4 = 0; c4 < 16; c4++){
        int cc = c4*4;
        float4 kA = *(const float4*)(kT + cc);
        float4 kB = *(const float4*)(kT + 64 + cc);
#pragma unroll
        for (int r = 0; r < 16; r++){
            float4 f4 = *(const float4*)&sf[r][cc];
            a1[r] += f4.x*kA.x + f4.y*kA.y + f4.z*kA.z + f4.w*kA.w;
            a2[r] += f4.x*kB.x + f4.y*kB.y + f4.z*kB.z + f4.w*kB.w;
        }
    }
#pragma unroll
    for (int r = 0; r < 16; r++){
        g_center[(p0 + r)*PC + j] = a1[r];
        g_point [(p0 + r)*PC + j] = a1[r] + a2[r];
    }
}

// ---------------- 4b) pure gather + assemble + bn/relu (per layer) ----------------
__global__ void k_asm(int l){
    int bn = blockIdx.x;
    int b  = bn >> 10;
    int tid = threadIdx.x;             // 256
    __shared__ float  s_sc[KNN][8];
    __shared__ float  s_S[8];
    __shared__ int    s_j[KNN];
    __shared__ float4 s_part[16][16];  // [kp][quad]
    if (tid < KNN) s_j[tid] = g_idx[bn*KNN + tid];
    {
        const float* src = &g_score[(l*BB*NN + bn)*KNN*MM];
        if (tid < KNN*MM) ((float*)s_sc)[tid] = src[tid];
    }
    __syncthreads();
    if (tid < 8){
        float s = 0.f;
#pragma unroll
        for (int k = 0; k < KNN; k++) s += s_sc[k][tid];
        s_S[tid] = s;
    }
    int q  = tid & 15;                 // o-quad: channels 4q..4q+3
    int kp = tid >> 4;                 // k partition 0..15
    float4 acc = make_float4(0.f, 0.f, 0.f, 0.f);
    for (int k = kp; k < KNN; k += 16){
        const float* pr = &g_point[(b*NN + s_j[k])*PC + 4*q];
#pragma unroll
        for (int m = 0; m < 8; m++){
            float s = s_sc[k][m];
            float4 p4 = *(const float4*)(pr + m*OO);
            acc.x += s*p4.x; acc.y += s*p4.y; acc.z += s*p4.z; acc.w += s*p4.w;
        }
    }
    s_part[kp][q] = acc;
    __syncthreads();
    if (tid < OO){
        int o = tid, qq = o >> 2, cc = o & 3;
        float a = 0.f;
#pragma unroll
        for (int kp2 = 0; kp2 < 16; kp2++){
            const float* pp = (const float*)&s_part[kp2][qq];
            a += pp[cc];
        }
        const float* cr = &g_center[bn*PC + o];
#pragma unroll
        for (int m = 0; m < 8; m++) a -= s_S[m]*cr[m*OO];
        g_feats[bn*FE + (l+1)*OO + o] = fmaxf(a*BN_SCALE, 0.f);
    }
}

// ---------------- 5) final GEMM + max ----------------
__global__ void k_final(const float* __restrict__ convt_w, float* __restrict__ out){
    __shared__ float sxx[32][FE];      // 40 KB
    int p0 = blockIdx.x*32;
    int b  = p0 >> 10;
    int o  = threadIdx.x;              // 512 columns
    {
        const float4* src = (const float4*)(g_feats + p0*FE);
        float4* dst = (float4*)&sxx[0][0];
        for (int q = threadIdx.x; q < 32*FE/4; q += 512) dst[q] = src[q];
    }
    __syncthreads();
    float acc[32];
#pragma unroll
    for (int r = 0; r < 32; r++) acc[r] = 0.f;
    const float* w = convt_w + o*FE;
#pragma unroll 4
    for (int c4 = 0; c4 < FE/4; c4++){
        int cc = c4*4;
        float4 w4 = *(const float4*)(w + cc);
#pragma unroll
        for (int r = 0; r < 32; r++){
            float4 x4 = *(const float4*)&sxx[r][cc];
            acc[r] += x4.x*w4.x + x4.y*w4.y + x4.z*w4.z + x4.w*w4.w;
        }
    }
    float mx = 0.f;
#pragma unroll
    for (int r = 0; r < 32; r++) mx = fmaxf(mx, acc[r]*BN_SCALE);  // relu folded
    atomicMax((int*)&out[b*PC + o], __float_as_int(mx));           // nonneg floats
}

// ---------------- launch ----------------
extern "C" void kernel_launch(void* const* d_in, const int* in_sizes, int n_in,
                              void* d_out, int out_size){
    const float* x       = (const float*)d_in[0];
    const float* conv1_w = (const float*)d_in[3];
    const float* conv1_b = (const float*)d_in[4];
    const float* sn_hw   = (const float*)d_in[5];
    const float* sn_ow   = (const float*)d_in[6];
    const float* sn_ob   = (const float*)d_in[7];
    const float* mats    = (const float*)d_in[8];
    const float* convt_w = (const float*)d_in[9];
    float* out = (float*)d_out;

    k_prep<<<(BB*NN + 255)/256, 256>>>(x, out);
    k_ktr<<<(4*PC*128 + 255)/256, 256>>>(mats);
    k_knn<<<BB*NN, 256>>>();
    k_edge<<<BB*NN, 128>>>(conv1_w, conv1_b, sn_hw, sn_ow, sn_ob);
    for (int l = 0; l < 4; l++){
        k_point<<<BB*NN/16, 512>>>(l);
        k_asm<<<BB*NN, 256>>>(l);
    }
    k_final<<<BB*NN/32, 512>>>(convt_w, out);
}